// round 2
// baseline (speedup 1.0000x reference)
#include <cuda_runtime.h>
#include <math.h>

// Problem constants
#define BB 8
#define NN 262144
#define CC 23
#define GG 10

#define THREADS 256
#define ITERS 8
#define ROWS_PER_BLOCK (THREADS * ITERS)      // 2048
#define CHUNKS (NN / ROWS_PER_BLOCK)          // 128
#define GRID (BB * CHUNKS)                    // 1024
#define TILE_FLOATS (THREADS * CC)            // 5888
#define TILE_VEC4 (TILE_FLOATS / 4)           // 1472 (exact: 5888 % 4 == 0)

// Scratch: per-(b, chunk) group sums. No device allocation allowed -> static global.
__device__ float g_partial[BB * CHUNKS * GG];

__global__ __launch_bounds__(THREADS) void group_sum_kernel(const float* __restrict__ inp) {
    __shared__ float tile[TILE_FLOATS];
    __shared__ float wsum[THREADS / 32][GG];

    const int tid = threadIdx.x;
    const int b = blockIdx.x >> 7;        // / CHUNKS
    const int chunk = blockIdx.x & 127;   // % CHUNKS
    const size_t row_base = (size_t)b * NN + (size_t)chunk * ROWS_PER_BLOCK;

    float a0 = 0.f, a1 = 0.f, a2 = 0.f, a3 = 0.f, a4 = 0.f;
    float a5 = 0.f, a6 = 0.f, a7 = 0.f, a8 = 0.f, a9 = 0.f;

    for (int it = 0; it < ITERS; it++) {
        // Coalesced float4 staging of 256 contiguous rows (tile base is 16B aligned:
        // row offset is a multiple of 256, 256*23*4 = 23552 bytes % 16 == 0).
        const float4* __restrict__ src =
            reinterpret_cast<const float4*>(inp + (row_base + (size_t)it * THREADS) * CC);
        float4* dst = reinterpret_cast<float4*>(tile);
        #pragma unroll
        for (int i = tid; i < TILE_VEC4; i += THREADS)
            dst[i] = src[i];
        __syncthreads();

        // One row per thread from SMEM; stride-23 across lanes is bank-conflict-free.
        const float* row = &tile[tid * CC];
        float v[CC];
        #pragma unroll
        for (int c = 0; c < CC; c++) v[c] = row[c];

        const float s0 = v[0] + v[1];
        const float s1 = v[2] + v[3];
        const float s2 = v[4] + v[5] + v[6];
        const float s3 = v[7] + v[8];
        const float s4 = v[9] + v[10] + v[11];
        const float s5 = v[12] + v[13];
        const float s6 = v[14] + v[15] + v[16];
        const float s7 = v[17] + v[18];
        const float s8 = v[19] + v[20];
        const float s9 = v[21] + v[22];

        const float total = ((s0 + s1) + (s2 + s3)) + ((s4 + s5) + (s6 + s7)) + (s8 + s9);
        const float inv = 1.0f / total;

        a0 += s0 * inv; a1 += s1 * inv; a2 += s2 * inv; a3 += s3 * inv; a4 += s4 * inv;
        a5 += s5 * inv; a6 += s6 * inv; a7 += s7 * inv; a8 += s8 * inv; a9 += s9 * inv;
        __syncthreads();
    }

    // Block reduction: warp shuffle then per-warp SMEM, no atomics (deterministic).
    float acc[GG] = {a0, a1, a2, a3, a4, a5, a6, a7, a8, a9};
    const int lane = tid & 31;
    const int warp = tid >> 5;
    #pragma unroll
    for (int g = 0; g < GG; g++) {
        float x = acc[g];
        x += __shfl_down_sync(0xffffffffu, x, 16);
        x += __shfl_down_sync(0xffffffffu, x, 8);
        x += __shfl_down_sync(0xffffffffu, x, 4);
        x += __shfl_down_sync(0xffffffffu, x, 2);
        x += __shfl_down_sync(0xffffffffu, x, 1);
        if (lane == 0) wsum[warp][g] = x;
    }
    __syncthreads();
    if (tid < GG) {
        float s = 0.f;
        #pragma unroll
        for (int w = 0; w < THREADS / 32; w++) s += wsum[w][tid];
        g_partial[(b * CHUNKS + chunk) * GG + tid] = s;
    }
}

__global__ void finalize_kernel(const float* __restrict__ targets, float* __restrict__ out) {
    __shared__ float avg[BB * GG];
    __shared__ float klb[BB];
    const int t = threadIdx.x;

    if (t < BB * GG) {
        const int b = t / GG;
        const int g = t % GG;
        float s = 0.f;
        for (int c = 0; c < CHUNKS; c++)
            s += g_partial[(b * CHUNKS + c) * GG + g];
        avg[t] = s * (1.0f / (float)NN);
    }
    __syncthreads();

    if (t < BB) {
        float kl = 0.f;
        #pragma unroll
        for (int g = 0; g < GG; g++) {
            const float tg = targets[t * GG + g];
            kl += tg * (logf(tg) - logf(avg[t * GG + g]));
        }
        klb[t] = kl;
    }
    __syncthreads();

    if (t == 0) {
        float s = 0.f;
        #pragma unroll
        for (int b = 0; b < BB; b++) s += klb[b];
        out[0] = s / (float)(GG * BB);  // /G inside each kl_b, then mean over B
    }
}

extern "C" void kernel_launch(void* const* d_in, const int* in_sizes, int n_in,
                              void* d_out, int out_size) {
    const float* inp = (const float*)d_in[0];
    const float* tgt = (const float*)d_in[1];
    // Defensive: identify by size in case metadata order differs.
    if (n_in >= 2 && in_sizes[0] == BB * GG) {
        inp = (const float*)d_in[1];
        tgt = (const float*)d_in[0];
    }
    group_sum_kernel<<<GRID, THREADS>>>(inp);
    finalize_kernel<<<1, 128>>>(tgt, (float*)d_out);
}

// round 5
// speedup vs baseline: 1.3822x; 1.3822x over previous
#include <cuda_runtime.h>
#include <stdint.h>
#include <math.h>

// Problem constants
#define BB 8
#define NN 262144
#define CC 23
#define GG 10

#define THREADS 256
#define ITERS 8
#define ROWS_PER_BLOCK (THREADS * ITERS)      // 2048
#define CHUNKS (NN / ROWS_PER_BLOCK)          // 128
#define GRID (BB * CHUNKS)                    // 1024
#define TILE_FLOATS (THREADS * CC)            // 5888
#define TILE_VEC4 (TILE_FLOATS / 4)           // 1472

// Scratch: per-(b, chunk) group sums. No device allocation allowed -> static global.
__device__ float g_partial[BB * CHUNKS * GG];

__device__ __forceinline__ unsigned smem_u32(const void* p) {
    unsigned a;
    asm("{ .reg .u64 t; cvta.to.shared.u64 t, %1; cvt.u32.u64 %0, t; }" : "=r"(a) : "l"(p));
    return a;
}

__global__ __launch_bounds__(THREADS) void group_sum_kernel(const float* __restrict__ inp) {
    __shared__ float tile[2][TILE_FLOATS];
    __shared__ float wsum[THREADS / 32][GG];

    const int tid = threadIdx.x;
    const int b = blockIdx.x >> 7;        // / CHUNKS
    const int chunk = blockIdx.x & 127;   // % CHUNKS
    const size_t row_base = (size_t)b * NN + (size_t)chunk * ROWS_PER_BLOCK;

    const unsigned sbuf0 = smem_u32(&tile[0][0]);
    const unsigned sbuf1 = smem_u32(&tile[1][0]);

    // Issue async copy of tile `it` into buffer `buf`.
    auto issue_tile = [&](int it, int buf) {
        const float4* __restrict__ src =
            reinterpret_cast<const float4*>(inp + (row_base + (size_t)it * THREADS) * CC);
        const unsigned s = buf ? sbuf1 : sbuf0;
        #pragma unroll
        for (int i = tid; i < TILE_VEC4; i += THREADS) {
            asm volatile("cp.async.cg.shared.global [%0], [%1], 16;"
                         :: "r"(s + (unsigned)i * 16), "l"(src + i));
        }
        asm volatile("cp.async.commit_group;");
    };

    float a0 = 0.f, a1 = 0.f, a2 = 0.f, a3 = 0.f, a4 = 0.f;
    float a5 = 0.f, a6 = 0.f, a7 = 0.f, a8 = 0.f, a9 = 0.f;

    issue_tile(0, 0);

    for (int it = 0; it < ITERS; it++) {
        if (it + 1 < ITERS) {
            issue_tile(it + 1, (it + 1) & 1);
            asm volatile("cp.async.wait_group 1;");
        } else {
            asm volatile("cp.async.wait_group 0;");
        }
        __syncthreads();

        // One row per thread from SMEM; stride-23 across lanes is bank-conflict-free.
        const float* row = &tile[it & 1][tid * CC];
        float v[CC];
        #pragma unroll
        for (int c = 0; c < CC; c++) v[c] = row[c];

        const float s0 = v[0] + v[1];
        const float s1 = v[2] + v[3];
        const float s2 = v[4] + v[5] + v[6];
        const float s3 = v[7] + v[8];
        const float s4 = v[9] + v[10] + v[11];
        const float s5 = v[12] + v[13];
        const float s6 = v[14] + v[15] + v[16];
        const float s7 = v[17] + v[18];
        const float s8 = v[19] + v[20];
        const float s9 = v[21] + v[22];

        const float total = ((s0 + s1) + (s2 + s3)) + ((s4 + s5) + (s6 + s7)) + (s8 + s9);
        const float inv = 1.0f / total;

        a0 += s0 * inv; a1 += s1 * inv; a2 += s2 * inv; a3 += s3 * inv; a4 += s4 * inv;
        a5 += s5 * inv; a6 += s6 * inv; a7 += s7 * inv; a8 += s8 * inv; a9 += s9 * inv;
        __syncthreads();   // buffer (it&1) safe to overwrite at next issue
    }

    // Block reduction: warp shuffle then per-warp SMEM, no atomics (deterministic).
    float acc[GG] = {a0, a1, a2, a3, a4, a5, a6, a7, a8, a9};
    const int lane = tid & 31;
    const int warp = tid >> 5;
    #pragma unroll
    for (int g = 0; g < GG; g++) {
        float x = acc[g];
        x += __shfl_down_sync(0xffffffffu, x, 16);
        x += __shfl_down_sync(0xffffffffu, x, 8);
        x += __shfl_down_sync(0xffffffffu, x, 4);
        x += __shfl_down_sync(0xffffffffu, x, 2);
        x += __shfl_down_sync(0xffffffffu, x, 1);
        if (lane == 0) wsum[warp][g] = x;
    }
    __syncthreads();
    if (tid < GG) {
        float s = 0.f;
        #pragma unroll
        for (int w = 0; w < THREADS / 32; w++) s += wsum[w][tid];
        g_partial[(b * CHUNKS + chunk) * GG + tid] = s;
    }
}

#define FTHREADS 1024

__global__ __launch_bounds__(FTHREADS) void finalize_kernel(const float* __restrict__ targets,
                                                            float* __restrict__ out) {
    __shared__ float sh[BB * GG * CHUNKS];   // 10240 floats = 40 KB
    __shared__ float avg[BB * GG];
    __shared__ float klb[BB];
    const int t = threadIdx.x;               // 1024 = BB * CHUNKS

    // Stage all partials with high MLP: thread t = (b, chunk) loads its 10 floats
    // (contiguous 40B per thread -> coalesced across the warp) and transposes into
    // sh[(b*GG+g)*CHUNKS + chunk] so the per-(b,g) reduction reads contiguous SMEM.
    {
        const int b = t >> 7;
        const int chunk = t & 127;
        float v[GG];
        #pragma unroll
        for (int g = 0; g < GG; g++) v[g] = g_partial[t * GG + g];
        #pragma unroll
        for (int g = 0; g < GG; g++) sh[(b * GG + g) * CHUNKS + chunk] = v[g];
    }
    __syncthreads();

    if (t < BB * GG) {
        const float* p = &sh[t * CHUNKS];
        float r0 = 0.f, r1 = 0.f, r2 = 0.f, r3 = 0.f;
        #pragma unroll
        for (int c = 0; c < CHUNKS; c += 4) {
            r0 += p[c]; r1 += p[c + 1]; r2 += p[c + 2]; r3 += p[c + 3];
        }
        avg[t] = ((r0 + r1) + (r2 + r3)) * (1.0f / (float)NN);
    }
    __syncthreads();

    if (t < BB) {
        float kl = 0.f;
        #pragma unroll
        for (int g = 0; g < GG; g++) {
            const float tg = targets[t * GG + g];
            kl += tg * (logf(tg) - logf(avg[t * GG + g]));
        }
        klb[t] = kl;
    }
    __syncthreads();

    if (t == 0) {
        float s = 0.f;
        #pragma unroll
        for (int b = 0; b < BB; b++) s += klb[b];
        out[0] = s / (float)(GG * BB);
    }
}

extern "C" void kernel_launch(void* const* d_in, const int* in_sizes, int n_in,
                              void* d_out, int out_size) {
    const float* inp = (const float*)d_in[0];
    const float* tgt = (const float*)d_in[1];
    if (n_in >= 2 && in_sizes[0] == BB * GG) {   // defensive order check
        inp = (const float*)d_in[1];
        tgt = (const float*)d_in[0];
    }
    group_sum_kernel<<<GRID, THREADS>>>(inp);
    finalize_kernel<<<1, FTHREADS>>>(tgt, (float*)d_out);
}